// round 3
// baseline (speedup 1.0000x reference)
#include <cuda_runtime.h>

#define Bc 4
#define Lc 1024
#define Hc 8
#define Ec 64
#define BHc 32

// d_out packing (floats): V [B,L,H,E] | series [B,H,L,L] | prior [B,H,L,L] | sig [B,H,L,1]
#define OFF_SERIES 2097152
#define OFF_PRIOR  35651584
#define OFF_SIG    69206016

// scratch: p_density [B,H,L,E] (8 MB)
__device__ float g_p[BHc * Lc * Ec];

// ---------------------------------------------------------------------------
// Kernel 1: sig + p_density.  grid = BH*L blocks, 64 threads (one per e).
// sig chain computed ONCE per row in double (correctly-rounded at each of the
// reference's f32 intermediate rounding points) to bitwise-match XLA's
// sigmoid/pow; p chain uses _rn intrinsics to replicate the f32 op sequence.
// ---------------------------------------------------------------------------
__global__ void sig_p_kernel(const float* __restrict__ sigma,
                             const float* __restrict__ x,
                             float* __restrict__ out) {
    __shared__ float s_sig;
    int row = blockIdx.x;              // (b*H + h)*L + l
    int e   = threadIdx.x;
    int l   = row & (Lc - 1);
    int bh  = row >> 10;
    int b   = bh >> 3, h = bh & 7;

    if (e == 0) {
        float t = __fmul_rn(sigma[(b * Lc + l) * Hc + h], 5.0f);   // ref: sigma*5.0 (f32)
        double sd = 1.0 / (1.0 + exp(-(double)t));                 // sigmoid, correctly rounded
        float s = (float)sd;
        s = __fadd_rn(s, 1e-5f);                                   // ref: +1e-5 (f32)
        float p3 = (float)exp((double)s * 1.0986122886681098);     // 3^s, correctly rounded to f32
        float sg = __fadd_rn(p3, -1.0f);                           // ref: -1.0 (f32)
        s_sig = sg;
        out[OFF_SIG + row] = sg;
    }
    __syncthreads();
    float sg = s_sig;

    float xv  = x[((size_t)(b * Lc + l) * Hc + h) * Ec + e];
    float xsq = __fmul_rn(xv, xv);                 // ref: xt**2
    float s2  = __fmul_rn(sg, sg);                 // ref: sig**2
    float dnm = __fadd_rn(s2, s2);                 // ref: 2*sig**2 (exact *2)
    float a   = __fdiv_rn(xsq, dnm);               // correctly-rounded div
    float ex  = expf(-a);
    float cf  = __fdiv_rn(0.3989422804014327f, sg);
    float pd  = __fadd_rn(__fmul_rn(cf, ex), 1e-5f);
    g_p[(size_t)row * Ec + e] = pd;
}

// ---------------------------------------------------------------------------
// Kernel 2: prior = P @ P^T per (b,h).  128x128 tile, K=64 fully in smem.
// 256 threads = 8 warps. Warp w: rows 64*(w>>2)+[0..63] (broadcast operand),
// cols 32*(w&3)+lane (per-lane LDS.128, pitch 68 floats -> conflict-free).
// ---------------------------------------------------------------------------
__global__ void __launch_bounds__(256) prior_kernel(float* __restrict__ out) {
    extern __shared__ float sm[];
    float* Ar = sm;             // [128][68]
    float* Bn = sm + 128 * 68;  // [128][68]

    int tid = threadIdx.x;
    int bh  = blockIdx.y;
    int bi  = blockIdx.x >> 3;
    int bj  = blockIdx.x & 7;
    const float* P = g_p + (size_t)bh * Lc * Ec;

    for (int f = tid; f < 2048; f += 256) {
        int r = f >> 4, eq = f & 15;
        *(float4*)&Ar[r * 68 + eq * 4] = *(const float4*)&P[(size_t)(bi * 128 + r) * 64 + eq * 4];
        *(float4*)&Bn[r * 68 + eq * 4] = *(const float4*)&P[(size_t)(bj * 128 + r) * 64 + eq * 4];
    }
    __syncthreads();

    int w = tid >> 5, lane = tid & 31;
    int colb = 32 * (w & 3);
    int rowb = 64 * (w >> 2);

    float acc[64];
#pragma unroll
    for (int i = 0; i < 64; i++) acc[i] = 0.0f;

    for (int k4 = 0; k4 < 16; k4++) {
        float4 b4 = *(float4*)&Bn[(colb + lane) * 68 + k4 * 4];
#pragma unroll
        for (int rr = 0; rr < 64; rr++) {
            float4 a4 = *(float4*)&Ar[(rowb + rr) * 68 + k4 * 4];
            acc[rr] = fmaf(a4.w, b4.w, fmaf(a4.z, b4.z,
                      fmaf(a4.y, b4.y, fmaf(a4.x, b4.x, acc[rr]))));
        }
    }

    float* o = out + OFF_PRIOR + (size_t)bh * Lc * Lc;
    int col = bj * 128 + colb + lane;
#pragma unroll
    for (int rr = 0; rr < 64; rr++) {
        int rowg = bi * 128 + rowb + rr;
        o[(size_t)rowg * Lc + col] = acc[rr];   // lanes -> consecutive cols: coalesced
    }
}

// ---------------------------------------------------------------------------
// Kernel 3: fused causal attention per (bh, 32-row block).
// Full 32x1024 score panel lives in smem; series written once; V accumulated
// in registers. Causal tiles beyond r0+32 never computed.
// ---------------------------------------------------------------------------
__global__ void __launch_bounds__(256) attn_kernel(const float* __restrict__ qg,
                                                   const float* __restrict__ kg,
                                                   const float* __restrict__ vg,
                                                   float* __restrict__ out) {
    extern __shared__ float sm[];
    float* Sp = sm;                  // [32][1025] score/prob panel (pad 1025 -> conflict-free col writes)
    float* Qr = sm + 32 * 1025;      // [32][68]
    float* Kn = Qr + 32 * 68;        // [128][68], reused for V tiles

    int tid  = threadIdx.x;
    int w    = tid >> 5, lane = tid & 31;
    int rb   = 31 - blockIdx.x;      // big blocks first
    int bh   = blockIdx.y;
    int b    = bh >> 3, h = bh & 7;
    int r0   = rb * 32;
    int nt   = (rb >> 2) + 1;        // 128-wide tiles needed to cover s <= r0+31
    int n_s  = nt << 7;
    const float scale = 0.125f;      // 1/sqrt(64)

    // load Q rows r0..r0+31
    for (int f = tid; f < 512; f += 256) {
        int r = f >> 4, eq = f & 15;
        *(float4*)&Qr[r * 68 + eq * 4] =
            *(const float4*)&qg[((size_t)(b * Lc + r0 + r) * Hc + h) * Ec + eq * 4];
    }

    // ---- Phase 1: scores -> panel (rows = lanes, warp w owns cols w*16..w*16+15)
    for (int t = 0; t < nt; t++) {
        __syncthreads();             // prev tile consumed (and Q load visible on t=0)
        int s0 = t << 7;
        for (int f = tid; f < 2048; f += 256) {
            int s = f >> 4, eq = f & 15;
            *(float4*)&Kn[s * 68 + eq * 4] =
                *(const float4*)&kg[((size_t)(b * Lc + s0 + s) * Hc + h) * Ec + eq * 4];
        }
        __syncthreads();

        float acc[16];
#pragma unroll
        for (int j = 0; j < 16; j++) acc[j] = 0.0f;

#pragma unroll 4
        for (int k4 = 0; k4 < 16; k4++) {
            float4 a4 = *(float4*)&Qr[lane * 68 + k4 * 4];   // per-lane, conflict-free
#pragma unroll
            for (int j = 0; j < 16; j++) {
                float4 b4 = *(float4*)&Kn[(w * 16 + j) * 68 + k4 * 4];  // warp-broadcast
                acc[j] = fmaf(a4.w, b4.w, fmaf(a4.z, b4.z,
                         fmaf(a4.y, b4.y, fmaf(a4.x, b4.x, acc[j]))));
            }
        }

        int l = r0 + lane;
#pragma unroll
        for (int j = 0; j < 16; j++) {
            int s = s0 + w * 16 + j;
            Sp[lane * 1025 + s] = (s <= l) ? acc[j] * scale : -3.4e38f;
        }
    }
    __syncthreads();

    // ---- Phase 2: rowwise softmax (warp w handles rows 4w..4w+3), write series
    for (int rr = 0; rr < 4; rr++) {
        int r = w * 4 + rr;
        float* row = &Sp[r * 1025];

        float m = -3.4e38f;
        for (int s = lane; s < n_s; s += 32) m = fmaxf(m, row[s]);
#pragma unroll
        for (int o = 16; o > 0; o >>= 1) m = fmaxf(m, __shfl_xor_sync(0xffffffffu, m, o));

        float sum = 0.0f;
        for (int s = lane; s < n_s; s += 32) {
            float e = expf(row[s] - m);   // masked -3.4e38 -> exp underflows to exact 0
            row[s] = e;
            sum += e;
        }
#pragma unroll
        for (int o = 16; o > 0; o >>= 1) sum += __shfl_xor_sync(0xffffffffu, sum, o);

        float inv = 1.0f / sum;
        float* g = out + OFF_SERIES + ((size_t)bh * Lc + (r0 + r)) * Lc;
        for (int s = lane; s < n_s; s += 32) {
            float p = row[s] * inv;
            row[s] = p;
            g[s] = p;                    // coalesced
        }
        for (int s = n_s + lane; s < Lc; s += 32) g[s] = 0.0f;
    }

    // ---- Phase 3: V = series @ values (warp w rows 4w..4w+3 broadcast, cols = 2*lane)
    float va[4][2];
#pragma unroll
    for (int rr = 0; rr < 4; rr++) { va[rr][0] = 0.0f; va[rr][1] = 0.0f; }

    for (int t = 0; t < nt; t++) {
        __syncthreads();                 // prev tile consumed / Kn free after phase 1
        int s0 = t << 7;
        for (int f = tid; f < 2048; f += 256) {
            int s = f >> 4, eq = f & 15;
            *(float4*)&Kn[s * 68 + eq * 4] =
                *(const float4*)&vg[((size_t)(b * Lc + s0 + s) * Hc + h) * Ec + eq * 4];
        }
        __syncthreads();

#pragma unroll 8
        for (int ss = 0; ss < 128; ss++) {
            float2 v2 = *(float2*)&Kn[ss * 68 + 2 * lane];
            int s = s0 + ss;
#pragma unroll
            for (int rr = 0; rr < 4; rr++) {
                float pv = Sp[(w * 4 + rr) * 1025 + s];     // warp-broadcast
                va[rr][0] = fmaf(pv, v2.x, va[rr][0]);
                va[rr][1] = fmaf(pv, v2.y, va[rr][1]);
            }
        }
    }

#pragma unroll
    for (int rr = 0; rr < 4; rr++) {
        int l = r0 + w * 4 + rr;
        *(float2*)&out[((size_t)(b * Lc + l) * Hc + h) * Ec + 2 * lane] =
            make_float2(va[rr][0], va[rr][1]);              // coalesced
    }
}

// ---------------------------------------------------------------------------
extern "C" void kernel_launch(void* const* d_in, const int* in_sizes, int n_in,
                              void* d_out, int out_size) {
    const float* q     = (const float*)d_in[0];
    const float* k     = (const float*)d_in[1];
    const float* v     = (const float*)d_in[2];
    const float* sigma = (const float*)d_in[3];
    const float* x     = (const float*)d_in[4];
    float* out = (float*)d_out;

    const int SMEM_PRIOR = 2 * 128 * 68 * 4;                       // 69,632 B
    const int SMEM_ATTN  = (32 * 1025 + 32 * 68 + 128 * 68) * 4;   // 174,720 B

    cudaFuncSetAttribute(prior_kernel, cudaFuncAttributeMaxDynamicSharedMemorySize, SMEM_PRIOR);
    cudaFuncSetAttribute(attn_kernel,  cudaFuncAttributeMaxDynamicSharedMemorySize, SMEM_ATTN);

    sig_p_kernel<<<BHc * Lc, 64>>>(sigma, x, out);
    prior_kernel<<<dim3(64, BHc), 256, SMEM_PRIOR>>>(out);
    attn_kernel<<<dim3(32, BHc), 256, SMEM_ATTN>>>(q, k, v, out);
}